// round 9
// baseline (speedup 1.0000x reference)
#include <cuda_runtime.h>
#include <cuda_bf16.h>
#include <cstdint>

#define NUM_EXPERT 8
#define IN_FEAT 1024
#define OUT_FEAT 4096
#define N_TOKENS 4096

#define BM 128
#define BN 256
#define BKF 32                    // K floats per stage (= 128 bytes per row)
#define NCHUNK (IN_FEAT / BKF)    // 32
#define NSTAGE 4
#define NTHREADS 256

#define A_STAGE_BYTES (BM * 128)              // 16384
#define B_STAGE_BYTES (BN * 128)              // 32768
#define STAGE_BYTES   (A_STAGE_BYTES + B_STAGE_BYTES)   // 49152
#define SMEM_TOTAL    (NSTAGE * STAGE_BYTES)            // 196608

// Scratch (no allocations allowed).
__device__ int g_perm[N_TOKENS];
__device__ int g_cnt[NUM_EXPERT];
__device__ int g_off[NUM_EXPERT];
// Pre-permuted, tf32-rounded activations (sorted by expert). Padded by BM rows:
// the last tile of an expert may read up to BM-1 rows past off+cnt (discarded).
__device__ float g_a[(size_t)(N_TOKENS + BM) * IN_FEAT];

// ---------------------------------------------------------------------------
// Kernel 1: counting sort of tokens by expert (single block).
// ---------------------------------------------------------------------------
__global__ void build_perm_kernel(const int* __restrict__ gate) {
    __shared__ int s_cnt[NUM_EXPERT];
    __shared__ int s_base[NUM_EXPERT];
    int t = threadIdx.x;
    if (t < NUM_EXPERT) s_cnt[t] = 0;
    __syncthreads();
    for (int i = t; i < N_TOKENS; i += blockDim.x)
        atomicAdd(&s_cnt[gate[i]], 1);
    __syncthreads();
    if (t == 0) {
        int acc = 0;
        for (int e = 0; e < NUM_EXPERT; e++) {
            s_base[e] = acc;
            g_off[e] = acc;
            g_cnt[e] = s_cnt[e];
            acc += s_cnt[e];
        }
    }
    __syncthreads();
    for (int i = t; i < N_TOKENS; i += blockDim.x) {
        int e = gate[i];
        int pos = atomicAdd(&s_base[e], 1);
        g_perm[pos] = i;
    }
}

// ---------------------------------------------------------------------------
// Kernel 1b: gather inp rows through perm into g_a, rounding to tf32 (rna).
// ---------------------------------------------------------------------------
__global__ __launch_bounds__(256) void gather_cvt_kernel(const float* __restrict__ inp) {
    const int p   = blockIdx.x;                 // sorted position
    const int row = g_perm[p];
    const float4* src = (const float4*)(inp + (size_t)row * IN_FEAT);
    float4* dst       = (float4*)(g_a + (size_t)p * IN_FEAT);
    float4 v = src[threadIdx.x];
    uint32_t x0, x1, x2, x3;
    asm("cvt.rna.tf32.f32 %0, %1;" : "=r"(x0) : "f"(v.x));
    asm("cvt.rna.tf32.f32 %0, %1;" : "=r"(x1) : "f"(v.y));
    asm("cvt.rna.tf32.f32 %0, %1;" : "=r"(x2) : "f"(v.z));
    asm("cvt.rna.tf32.f32 %0, %1;" : "=r"(x3) : "f"(v.w));
    float4 o;
    o.x = __uint_as_float(x0); o.y = __uint_as_float(x1);
    o.z = __uint_as_float(x2); o.w = __uint_as_float(x3);
    dst[threadIdx.x] = o;
}

// ---------------------------------------------------------------------------
// helpers
// ---------------------------------------------------------------------------
__device__ __forceinline__ uint32_t smem_u32(const void* p) {
    uint32_t a;
    asm("{ .reg .u64 t; cvta.to.shared.u64 t, %1; cvt.u32.u64 %0, t; }" : "=r"(a) : "l"(p));
    return a;
}
__device__ __forceinline__ void cp16(uint32_t dst, const void* src) {
    asm volatile("cp.async.cg.shared.global [%0], [%1], 16;"
                 :: "r"(dst), "l"(src) : "memory");
}
__device__ __forceinline__ void cp_commit() {
    asm volatile("cp.async.commit_group;" ::: "memory");
}
__device__ __forceinline__ void cp_wait2() {
    asm volatile("cp.async.wait_group 2;" ::: "memory");
}
__device__ __forceinline__ void ldsm4(uint32_t& r0, uint32_t& r1, uint32_t& r2, uint32_t& r3,
                                      uint32_t addr) {
    asm volatile("ldmatrix.sync.aligned.m8n8.x4.shared.b16 {%0,%1,%2,%3}, [%4];"
                 : "=r"(r0), "=r"(r1), "=r"(r2), "=r"(r3) : "r"(addr));
}
__device__ __forceinline__ void mma_tf32(float& c0, float& c1, float& c2, float& c3,
                                         uint32_t a0, uint32_t a1, uint32_t a2, uint32_t a3,
                                         uint32_t b0, uint32_t b1) {
    asm volatile(
        "mma.sync.aligned.m16n8k8.row.col.f32.tf32.tf32.f32 "
        "{%0,%1,%2,%3}, {%4,%5,%6,%7}, {%8,%9}, {%0,%1,%2,%3};"
        : "+f"(c0), "+f"(c1), "+f"(c2), "+f"(c3)
        : "r"(a0), "r"(a1), "r"(a2), "r"(a3), "r"(b0), "r"(b1));
}

// ---------------------------------------------------------------------------
// Kernel 2: tf32 mma.sync grouped GEMM, 128x256 CTA tile, 4-stage pipeline,
// 1 CTA/SM. Warp tile 64x64 (2m x 4n warps).
//   C[m, n] = sum_k g_a[off + m, k] * weight[e, n, k]
// A pre-rounded (rna) in g_a; B raw f32 bits (HW tf32 truncation).
// ---------------------------------------------------------------------------
__global__ __launch_bounds__(NTHREADS, 1) void moe_gemm_mma_kernel(
    const float* __restrict__ weight,
    float* __restrict__ out)
{
    const int e   = blockIdx.z;
    const int cnt = g_cnt[e];
    const int mt  = blockIdx.y;
    if (mt * BM >= cnt) return;
    const int nt  = blockIdx.x;
    const int off = g_off[e];

    extern __shared__ char smem[];
    const uint32_t sbase = smem_u32(smem);

    const int tid  = threadIdx.x;
    const int wid  = tid >> 5;
    const int lane = tid & 31;
    const int wm   = (wid & 1) * 64;   // warp m-offset (2 warps in m)
    const int wn   = (wid >> 1) * 64;  // warp n-offset (4 warps in n)

    // ---- loader precompute ----
    const int lc  = tid & 7;
    const int sl  = (tid >> 3) & 7;
    const uint32_t swc = (uint32_t)((lc ^ sl) << 4);
    const int lr  = tid >> 3;                       // 0..31
    uint32_t a_off[4], b_off[8];
    const float* a_src[4];
    const float* b_src[8];
    const float* wB = weight + (size_t)e * OUT_FEAT * IN_FEAT
                             + (size_t)(nt * BN) * IN_FEAT;
    #pragma unroll
    for (int j = 0; j < 4; j++) {
        int r = lr + 32 * j;
        a_off[j] = (uint32_t)(r * 128) + swc;
        a_src[j] = g_a + (size_t)(off + mt * BM + r) * IN_FEAT + lc * 4;
    }
    #pragma unroll
    for (int j = 0; j < 8; j++) {
        int r = lr + 32 * j;
        b_off[j] = (uint32_t)(r * 128) + swc;
        b_src[j] = wB + (size_t)r * IN_FEAT + lc * 4;
    }

    // ---- prologue: fill stages 0..2 with chunks 0..2 ----
    #pragma unroll
    for (int i = 0; i < NSTAGE - 1; i++) {
        uint32_t sA = sbase + i * STAGE_BYTES;
        uint32_t sB = sA + A_STAGE_BYTES;
        #pragma unroll
        for (int j = 0; j < 4; j++) cp16(sA + a_off[j], a_src[j] + i * BKF);
        #pragma unroll
        for (int j = 0; j < 8; j++) cp16(sB + b_off[j], b_src[j] + i * BKF);
        cp_commit();
    }

    // ---- fragment addressing (tile-invariant) ----
    const int asel = lane & 7;
    const int aRowBase = wm + (lane & 7) + ((lane >> 3) & 1) * 8;
    const int aCLane   = (lane >> 4) & 1;
    const int bRowBase = wn + (lane & 7) + ((lane >> 4) & 1) * 8;
    const int bCLane   = (lane >> 3) & 1;

    uint32_t aRowOff[4], bRowOff[4];
    #pragma unroll
    for (int mi = 0; mi < 4; mi++) aRowOff[mi] = (uint32_t)((aRowBase + mi * 16) * 128);
    #pragma unroll
    for (int p = 0; p < 4; p++)    bRowOff[p]  = (uint32_t)((bRowBase + p * 16) * 128);

    uint32_t cA[4], cB[4];
    #pragma unroll
    for (int ks = 0; ks < 4; ks++) {
        cA[ks] = (uint32_t)((((2 * ks + aCLane) ^ asel)) << 4);
        cB[ks] = (uint32_t)((((2 * ks + bCLane) ^ asel)) << 4);
    }

    float acc[4][8][4];
    #pragma unroll
    for (int mi = 0; mi < 4; mi++)
        #pragma unroll
        for (int ni = 0; ni < 8; ni++)
            #pragma unroll
            for (int r = 0; r < 4; r++)
                acc[mi][ni][r] = 0.0f;

    // ---- main loop over 32 K-chunks ----
    for (int i = 0; i < NCHUNK; i++) {
        cp_wait2();                  // chunk i resident (commits=3+i, allow 2 pending)
        __syncthreads();

        int nx = i + NSTAGE - 1;
        if (nx < NCHUNK) {
            uint32_t sA = sbase + (nx % NSTAGE) * STAGE_BYTES;
            uint32_t sB = sA + A_STAGE_BYTES;
            #pragma unroll
            for (int j = 0; j < 4; j++) cp16(sA + a_off[j], a_src[j] + nx * BKF);
            #pragma unroll
            for (int j = 0; j < 8; j++) cp16(sB + b_off[j], b_src[j] + nx * BKF);
        }
        cp_commit();

        const uint32_t sA = sbase + (i % NSTAGE) * STAGE_BYTES;
        const uint32_t sB = sA + A_STAGE_BYTES;

        #pragma unroll
        for (int ks = 0; ks < 4; ks++) {
            uint32_t a[4][4], b[8][2];
            #pragma unroll
            for (int mi = 0; mi < 4; mi++)
                ldsm4(a[mi][0], a[mi][1], a[mi][2], a[mi][3], sA + aRowOff[mi] + cA[ks]);
            #pragma unroll
            for (int p = 0; p < 4; p++) {
                uint32_t t0, t1, t2, t3;
                ldsm4(t0, t1, t2, t3, sB + bRowOff[p] + cB[ks]);
                b[2 * p][0] = t0; b[2 * p][1] = t1;
                b[2 * p + 1][0] = t2; b[2 * p + 1][1] = t3;
            }
            #pragma unroll
            for (int mi = 0; mi < 4; mi++)
                #pragma unroll
                for (int ni = 0; ni < 8; ni++)
                    mma_tf32(acc[mi][ni][0], acc[mi][ni][1], acc[mi][ni][2], acc[mi][ni][3],
                             a[mi][0], a[mi][1], a[mi][2], a[mi][3],
                             b[ni][0], b[ni][1]);
        }
    }

    // ---- epilogue: scatter valid rows back through perm ----
    const int q  = lane >> 2;
    const int cc = 2 * (lane & 3);
    #pragma unroll
    for (int mi = 0; mi < 4; mi++) {
        #pragma unroll
        for (int half = 0; half < 2; half++) {
            const int r = wm + mi * 16 + q + half * 8;
            const int m = mt * BM + r;
            if (m < cnt) {
                float* orow = out + (size_t)g_perm[off + m] * OUT_FEAT
                                  + nt * BN + wn + cc;
                #pragma unroll
                for (int ni = 0; ni < 8; ni++) {
                    float2 v = make_float2(acc[mi][ni][half * 2],
                                           acc[mi][ni][half * 2 + 1]);
                    *(float2*)(orow + ni * 8) = v;
                }
            }
        }
    }
}

extern "C" void kernel_launch(void* const* d_in, const int* in_sizes, int n_in,
                              void* d_out, int out_size) {
    const float* inp    = (const float*)d_in[0];   // [N_TOKENS, IN_FEAT] f32
    const int*   gate   = (const int*)d_in[1];     // [N_TOKENS] i32
    const float* weight = (const float*)d_in[2];   // [NUM_EXPERT, OUT_FEAT, IN_FEAT] f32
    float* out = (float*)d_out;                    // [N_TOKENS, OUT_FEAT] f32

    cudaFuncSetAttribute(moe_gemm_mma_kernel,
                         cudaFuncAttributeMaxDynamicSharedMemorySize, SMEM_TOTAL);

    build_perm_kernel<<<1, 256>>>(gate);
    gather_cvt_kernel<<<N_TOKENS, 256>>>(inp);

    dim3 grid(OUT_FEAT / BN, N_TOKENS / BM, NUM_EXPERT);
    moe_gemm_mma_kernel<<<grid, NTHREADS, SMEM_TOTAL>>>(weight, out);
}

// round 11
// speedup vs baseline: 1.0851x; 1.0851x over previous
#include <cuda_runtime.h>
#include <cuda_bf16.h>
#include <cstdint>

#define NUM_EXPERT 8
#define IN_FEAT 1024
#define OUT_FEAT 4096
#define N_TOKENS 4096

#define BM 128
#define BN 128
#define BKF 32                    // K floats per stage (= 128 bytes per row)
#define NCHUNK (IN_FEAT / BKF)    // 32
#define NSTAGE 3
#define NTHREADS 128              // 4 warps, each owning a 64x64 sub-tile

#define A_STAGE_BYTES (BM * 128)              // 16384
#define STAGE_BYTES   (2 * BM * 128)          // 32768 (A then B)
#define SMEM_TOTAL    (NSTAGE * STAGE_BYTES)  // 98304

// Scratch (no allocations allowed).
__device__ int g_perm[N_TOKENS];
__device__ int g_cnt[NUM_EXPERT];
__device__ int g_off[NUM_EXPERT];
// Pre-permuted, tf32-rounded activations (sorted by expert). Padded by BM rows:
// the last tile of an expert may read up to BM-1 rows past off+cnt (discarded).
__device__ float g_a[(size_t)(N_TOKENS + BM) * IN_FEAT];

// ---------------------------------------------------------------------------
// Kernel 1: counting sort of tokens by expert (single block).
// ---------------------------------------------------------------------------
__global__ void build_perm_kernel(const int* __restrict__ gate) {
    __shared__ int s_cnt[NUM_EXPERT];
    __shared__ int s_base[NUM_EXPERT];
    int t = threadIdx.x;
    if (t < NUM_EXPERT) s_cnt[t] = 0;
    __syncthreads();
    for (int i = t; i < N_TOKENS; i += blockDim.x)
        atomicAdd(&s_cnt[gate[i]], 1);
    __syncthreads();
    if (t == 0) {
        int acc = 0;
        for (int e = 0; e < NUM_EXPERT; e++) {
            s_base[e] = acc;
            g_off[e] = acc;
            g_cnt[e] = s_cnt[e];
            acc += s_cnt[e];
        }
    }
    __syncthreads();
    for (int i = t; i < N_TOKENS; i += blockDim.x) {
        int e = gate[i];
        int pos = atomicAdd(&s_base[e], 1);
        g_perm[pos] = i;
    }
}

// ---------------------------------------------------------------------------
// Kernel 1b: gather inp rows through perm into g_a, rounding to tf32 (rna).
// ---------------------------------------------------------------------------
__global__ __launch_bounds__(256) void gather_cvt_kernel(const float* __restrict__ inp) {
    const int p   = blockIdx.x;                 // sorted position
    const int row = g_perm[p];
    const float4* src = (const float4*)(inp + (size_t)row * IN_FEAT);
    float4* dst       = (float4*)(g_a + (size_t)p * IN_FEAT);
    float4 v = src[threadIdx.x];
    uint32_t x0, x1, x2, x3;
    asm("cvt.rna.tf32.f32 %0, %1;" : "=r"(x0) : "f"(v.x));
    asm("cvt.rna.tf32.f32 %0, %1;" : "=r"(x1) : "f"(v.y));
    asm("cvt.rna.tf32.f32 %0, %1;" : "=r"(x2) : "f"(v.z));
    asm("cvt.rna.tf32.f32 %0, %1;" : "=r"(x3) : "f"(v.w));
    float4 o;
    o.x = __uint_as_float(x0); o.y = __uint_as_float(x1);
    o.z = __uint_as_float(x2); o.w = __uint_as_float(x3);
    dst[threadIdx.x] = o;
}

// ---------------------------------------------------------------------------
// helpers
// ---------------------------------------------------------------------------
__device__ __forceinline__ uint32_t smem_u32(const void* p) {
    uint32_t a;
    asm("{ .reg .u64 t; cvta.to.shared.u64 t, %1; cvt.u32.u64 %0, t; }" : "=r"(a) : "l"(p));
    return a;
}
__device__ __forceinline__ void cp16(uint32_t dst, const void* src) {
    asm volatile("cp.async.cg.shared.global [%0], [%1], 16;"
                 :: "r"(dst), "l"(src) : "memory");
}
__device__ __forceinline__ void cp_commit() {
    asm volatile("cp.async.commit_group;" ::: "memory");
}
__device__ __forceinline__ void cp_wait1() {
    asm volatile("cp.async.wait_group 1;" ::: "memory");
}
__device__ __forceinline__ void ldsm4(uint32_t& r0, uint32_t& r1, uint32_t& r2, uint32_t& r3,
                                      uint32_t addr) {
    asm volatile("ldmatrix.sync.aligned.m8n8.x4.shared.b16 {%0,%1,%2,%3}, [%4];"
                 : "=r"(r0), "=r"(r1), "=r"(r2), "=r"(r3) : "r"(addr));
}
__device__ __forceinline__ void mma_tf32(float& c0, float& c1, float& c2, float& c3,
                                         uint32_t a0, uint32_t a1, uint32_t a2, uint32_t a3,
                                         uint32_t b0, uint32_t b1) {
    asm volatile(
        "mma.sync.aligned.m16n8k8.row.col.f32.tf32.tf32.f32 "
        "{%0,%1,%2,%3}, {%4,%5,%6,%7}, {%8,%9}, {%0,%1,%2,%3};"
        : "+f"(c0), "+f"(c1), "+f"(c2), "+f"(c3)
        : "r"(a0), "r"(a1), "r"(a2), "r"(a3), "r"(b0), "r"(b1));
}

// ---------------------------------------------------------------------------
// Kernel 2: tf32 mma.sync grouped GEMM. 128x128 CTA tile, 4 warps @ 64x64,
// 128 threads, 3-stage cp.async pipeline, 2 CTAs/SM.
//   C[m, n] = sum_k g_a[off + m, k] * weight[e, n, k]
// A pre-rounded (rna) in g_a; B raw f32 bits (HW tf32 truncation).
// ---------------------------------------------------------------------------
__global__ __launch_bounds__(NTHREADS, 2) void moe_gemm_mma_kernel(
    const float* __restrict__ weight,
    float* __restrict__ out)
{
    const int e   = blockIdx.z;
    const int cnt = g_cnt[e];
    const int mt  = blockIdx.y;
    if (mt * BM >= cnt) return;
    const int nt  = blockIdx.x;
    const int off = g_off[e];

    extern __shared__ char smem[];
    const uint32_t sbase = smem_u32(smem);

    const int tid  = threadIdx.x;
    const int wid  = tid >> 5;
    const int lane = tid & 31;
    const int wm   = (wid & 1) * 64;   // warp m-offset (2 warps in m)
    const int wn   = (wid >> 1) * 64;  // warp n-offset (2 warps in n)

    // ---- loader precompute: 8 A + 8 B cp16 per thread per stage ----
    const int lc  = tid & 7;           // 16B column (0..7)
    const int lr  = tid >> 3;          // base row (0..15)
    const uint32_t swc = (uint32_t)((lc ^ (lr & 7)) << 4);   // (lr+16j)&7 == lr&7
    uint32_t d_off[8];
    const float* a_src[8];
    const float* b_src[8];
    const float* wB = weight + (size_t)e * OUT_FEAT * IN_FEAT
                             + (size_t)(nt * BN) * IN_FEAT;
    #pragma unroll
    for (int j = 0; j < 8; j++) {
        int r = lr + 16 * j;
        d_off[j] = (uint32_t)(r * 128) + swc;
        a_src[j] = g_a + (size_t)(off + mt * BM + r) * IN_FEAT + lc * 4;
        b_src[j] = wB + (size_t)r * IN_FEAT + lc * 4;
    }

    // ---- prologue: fill stages 0..1 with chunks 0..1 ----
    #pragma unroll
    for (int i = 0; i < NSTAGE - 1; i++) {
        uint32_t sA = sbase + i * STAGE_BYTES;
        uint32_t sB = sA + A_STAGE_BYTES;
        #pragma unroll
        for (int j = 0; j < 8; j++) {
            cp16(sA + d_off[j], a_src[j] + i * BKF);
            cp16(sB + d_off[j], b_src[j] + i * BKF);
        }
        cp_commit();
    }

    // ---- fragment addressing (tile-invariant) ----
    const int asel = lane & 7;
    const int aRowBase = wm + (lane & 7) + ((lane >> 3) & 1) * 8;
    const int aCLane   = (lane >> 4) & 1;
    const int bRowBase = wn + (lane & 7) + ((lane >> 4) & 1) * 8;
    const int bCLane   = (lane >> 3) & 1;

    uint32_t aRowOff[4], bRowOff[4];
    #pragma unroll
    for (int mi = 0; mi < 4; mi++) aRowOff[mi] = (uint32_t)((aRowBase + mi * 16) * 128);
    #pragma unroll
    for (int p = 0; p < 4; p++)    bRowOff[p]  = (uint32_t)((bRowBase + p * 16) * 128);

    uint32_t cA[4], cB[4];
    #pragma unroll
    for (int ks = 0; ks < 4; ks++) {
        cA[ks] = (uint32_t)((((2 * ks + aCLane) ^ asel)) << 4);
        cB[ks] = (uint32_t)((((2 * ks + bCLane) ^ asel)) << 4);
    }

    float acc[4][8][4];
    #pragma unroll
    for (int mi = 0; mi < 4; mi++)
        #pragma unroll
        for (int ni = 0; ni < 8; ni++)
            #pragma unroll
            for (int r = 0; r < 4; r++)
                acc[mi][ni][r] = 0.0f;

    // ---- main loop over 32 K-chunks ----
    for (int i = 0; i < NCHUNK; i++) {
        cp_wait1();
        __syncthreads();

        int nx = i + NSTAGE - 1;
        if (nx < NCHUNK) {
            uint32_t sA = sbase + (nx % NSTAGE) * STAGE_BYTES;
            uint32_t sB = sA + A_STAGE_BYTES;
            #pragma unroll
            for (int j = 0; j < 8; j++) {
                cp16(sA + d_off[j], a_src[j] + nx * BKF);
                cp16(sB + d_off[j], b_src[j] + nx * BKF);
            }
        }
        cp_commit();

        const uint32_t sA = sbase + (i % NSTAGE) * STAGE_BYTES;
        const uint32_t sB = sA + A_STAGE_BYTES;

        #pragma unroll
        for (int ks = 0; ks < 4; ks++) {
            uint32_t a[4][4], b[8][2];
            #pragma unroll
            for (int mi = 0; mi < 4; mi++)
                ldsm4(a[mi][0], a[mi][1], a[mi][2], a[mi][3], sA + aRowOff[mi] + cA[ks]);
            #pragma unroll
            for (int p = 0; p < 4; p++) {
                uint32_t t0, t1, t2, t3;
                ldsm4(t0, t1, t2, t3, sB + bRowOff[p] + cB[ks]);
                b[2 * p][0] = t0; b[2 * p][1] = t1;
                b[2 * p + 1][0] = t2; b[2 * p + 1][1] = t3;
            }
            #pragma unroll
            for (int mi = 0; mi < 4; mi++)
                #pragma unroll
                for (int ni = 0; ni < 8; ni++)
                    mma_tf32(acc[mi][ni][0], acc[mi][ni][1], acc[mi][ni][2], acc[mi][ni][3],
                             a[mi][0], a[mi][1], a[mi][2], a[mi][3],
                             b[ni][0], b[ni][1]);
        }
    }

    // ---- epilogue: scatter valid rows back through perm ----
    const int q  = lane >> 2;
    const int cc = 2 * (lane & 3);
    #pragma unroll
    for (int mi = 0; mi < 4; mi++) {
        #pragma unroll
        for (int half = 0; half < 2; half++) {
            const int r = wm + mi * 16 + q + half * 8;
            const int m = mt * BM + r;
            if (m < cnt) {
                float* orow = out + (size_t)g_perm[off + m] * OUT_FEAT
                                  + nt * BN + wn + cc;
                #pragma unroll
                for (int ni = 0; ni < 8; ni++) {
                    float2 v = make_float2(acc[mi][ni][half * 2],
                                           acc[mi][ni][half * 2 + 1]);
                    *(float2*)(orow + ni * 8) = v;
                }
            }
        }
    }
}

extern "C" void kernel_launch(void* const* d_in, const int* in_sizes, int n_in,
                              void* d_out, int out_size) {
    const float* inp    = (const float*)d_in[0];   // [N_TOKENS, IN_FEAT] f32
    const int*   gate   = (const int*)d_in[1];     // [N_TOKENS] i32
    const float* weight = (const float*)d_in[2];   // [NUM_EXPERT, OUT_FEAT, IN_FEAT] f32
    float* out = (float*)d_out;                    // [N_TOKENS, OUT_FEAT] f32

    cudaFuncSetAttribute(moe_gemm_mma_kernel,
                         cudaFuncAttributeMaxDynamicSharedMemorySize, SMEM_TOTAL);

    build_perm_kernel<<<1, 256>>>(gate);
    gather_cvt_kernel<<<N_TOKENS, 256>>>(inp);

    dim3 grid(OUT_FEAT / BN, N_TOKENS / BM, NUM_EXPERT);
    moe_gemm_mma_kernel<<<grid, NTHREADS, SMEM_TOTAL>>>(weight, out);
}

// round 12
// speedup vs baseline: 1.0852x; 1.0002x over previous
#include <cuda_runtime.h>
#include <cuda_bf16.h>
#include <cstdint>

#define NUM_EXPERT 8
#define IN_FEAT 1024
#define OUT_FEAT 4096
#define N_TOKENS 4096

#define BM 128
#define BN 128
#define BKF 32                    // K floats per stage (= 128 bytes per row)
#define NCHUNK (IN_FEAT / BKF)    // 32
#define NSTAGE 3
#define NTHREADS 128              // 4 warps, each owning a 64x64 sub-tile

#define A_STAGE_BYTES (BM * 128)              // 16384
#define STAGE_BYTES   (2 * BM * 128)          // 32768 (A then B)
#define SMEM_TOTAL    (NSTAGE * STAGE_BYTES)  // 98304

// Scratch (no allocations allowed).
__device__ int g_perm[N_TOKENS];
__device__ int g_cnt[NUM_EXPERT];
__device__ int g_off[NUM_EXPERT];
// Pre-permuted, tf32-rounded activations (sorted by expert). Padded by BM rows:
// the last tile of an expert may read up to BM-1 rows past off+cnt (discarded).
__device__ float g_a[(size_t)(N_TOKENS + BM) * IN_FEAT];

// ---------------------------------------------------------------------------
// Kernel 1: counting sort of tokens by expert (single block).
// ---------------------------------------------------------------------------
__global__ void build_perm_kernel(const int* __restrict__ gate) {
    __shared__ int s_cnt[NUM_EXPERT];
    __shared__ int s_base[NUM_EXPERT];
    int t = threadIdx.x;
    if (t < NUM_EXPERT) s_cnt[t] = 0;
    __syncthreads();
    for (int i = t; i < N_TOKENS; i += blockDim.x)
        atomicAdd(&s_cnt[gate[i]], 1);
    __syncthreads();
    if (t == 0) {
        int acc = 0;
        for (int e = 0; e < NUM_EXPERT; e++) {
            s_base[e] = acc;
            g_off[e] = acc;
            g_cnt[e] = s_cnt[e];
            acc += s_cnt[e];
        }
    }
    __syncthreads();
    for (int i = t; i < N_TOKENS; i += blockDim.x) {
        int e = gate[i];
        int pos = atomicAdd(&s_base[e], 1);
        g_perm[pos] = i;
    }
}

// ---------------------------------------------------------------------------
// Kernel 1b: gather inp rows through perm into g_a, rounding to tf32 (rna).
// ---------------------------------------------------------------------------
__global__ __launch_bounds__(256) void gather_cvt_kernel(const float* __restrict__ inp) {
    const int p   = blockIdx.x;                 // sorted position
    const int row = g_perm[p];
    const float4* src = (const float4*)(inp + (size_t)row * IN_FEAT);
    float4* dst       = (float4*)(g_a + (size_t)p * IN_FEAT);
    float4 v = src[threadIdx.x];
    uint32_t x0, x1, x2, x3;
    asm("cvt.rna.tf32.f32 %0, %1;" : "=r"(x0) : "f"(v.x));
    asm("cvt.rna.tf32.f32 %0, %1;" : "=r"(x1) : "f"(v.y));
    asm("cvt.rna.tf32.f32 %0, %1;" : "=r"(x2) : "f"(v.z));
    asm("cvt.rna.tf32.f32 %0, %1;" : "=r"(x3) : "f"(v.w));
    float4 o;
    o.x = __uint_as_float(x0); o.y = __uint_as_float(x1);
    o.z = __uint_as_float(x2); o.w = __uint_as_float(x3);
    dst[threadIdx.x] = o;
}

// ---------------------------------------------------------------------------
// helpers
// ---------------------------------------------------------------------------
__device__ __forceinline__ uint32_t smem_u32(const void* p) {
    uint32_t a;
    asm("{ .reg .u64 t; cvta.to.shared.u64 t, %1; cvt.u32.u64 %0, t; }" : "=r"(a) : "l"(p));
    return a;
}
__device__ __forceinline__ void cp16(uint32_t dst, const void* src) {
    asm volatile("cp.async.cg.shared.global [%0], [%1], 16;"
                 :: "r"(dst), "l"(src) : "memory");
}
__device__ __forceinline__ void cp_commit() {
    asm volatile("cp.async.commit_group;" ::: "memory");
}
__device__ __forceinline__ void cp_wait1() {
    asm volatile("cp.async.wait_group 1;" ::: "memory");
}
__device__ __forceinline__ void ldsm4(uint32_t& r0, uint32_t& r1, uint32_t& r2, uint32_t& r3,
                                      uint32_t addr) {
    asm volatile("ldmatrix.sync.aligned.m8n8.x4.shared.b16 {%0,%1,%2,%3}, [%4];"
                 : "=r"(r0), "=r"(r1), "=r"(r2), "=r"(r3) : "r"(addr));
}
__device__ __forceinline__ void mma_tf32(float& c0, float& c1, float& c2, float& c3,
                                         uint32_t a0, uint32_t a1, uint32_t a2, uint32_t a3,
                                         uint32_t b0, uint32_t b1) {
    asm volatile(
        "mma.sync.aligned.m16n8k8.row.col.f32.tf32.tf32.f32 "
        "{%0,%1,%2,%3}, {%4,%5,%6,%7}, {%8,%9}, {%0,%1,%2,%3};"
        : "+f"(c0), "+f"(c1), "+f"(c2), "+f"(c3)
        : "r"(a0), "r"(a1), "r"(a2), "r"(a3), "r"(b0), "r"(b1));
}
__device__ __forceinline__ void stg_cs_v2(float* p, float x, float y) {
    asm volatile("st.global.cs.v2.f32 [%0], {%1, %2};"
                 :: "l"(p), "f"(x), "f"(y) : "memory");
}

// ---------------------------------------------------------------------------
// Kernel 2: tf32 mma.sync grouped GEMM. 128x128 CTA tile, 4 warps @ 64x64,
// 128 threads, 3-stage cp.async pipeline, 2 CTAs/SM. Fragments double-buffered
// across ks steps so LDSM latency hides behind the previous step's MMAs.
//   C[m, n] = sum_k g_a[off + m, k] * weight[e, n, k]
// A pre-rounded (rna) in g_a; B raw f32 bits (HW tf32 truncation).
// ---------------------------------------------------------------------------
__global__ __launch_bounds__(NTHREADS, 2) void moe_gemm_mma_kernel(
    const float* __restrict__ weight,
    float* __restrict__ out)
{
    const int e   = blockIdx.z;
    const int cnt = g_cnt[e];
    const int mt  = blockIdx.y;
    if (mt * BM >= cnt) return;
    const int nt  = blockIdx.x;
    const int off = g_off[e];

    extern __shared__ char smem[];
    const uint32_t sbase = smem_u32(smem);

    const int tid  = threadIdx.x;
    const int wid  = tid >> 5;
    const int lane = tid & 31;
    const int wm   = (wid & 1) * 64;   // warp m-offset (2 warps in m)
    const int wn   = (wid >> 1) * 64;  // warp n-offset (2 warps in n)

    // ---- loader precompute: 8 A + 8 B cp16 per thread per stage ----
    const int lc  = tid & 7;           // 16B column (0..7)
    const int lr  = tid >> 3;          // base row (0..15)
    const uint32_t swc = (uint32_t)((lc ^ (lr & 7)) << 4);   // (lr+16j)&7 == lr&7
    uint32_t d_off[8];
    const float* a_src[8];
    const float* b_src[8];
    const float* wB = weight + (size_t)e * OUT_FEAT * IN_FEAT
                             + (size_t)(nt * BN) * IN_FEAT;
    #pragma unroll
    for (int j = 0; j < 8; j++) {
        int r = lr + 16 * j;
        d_off[j] = (uint32_t)(r * 128) + swc;
        a_src[j] = g_a + (size_t)(off + mt * BM + r) * IN_FEAT + lc * 4;
        b_src[j] = wB + (size_t)r * IN_FEAT + lc * 4;
    }

    // ---- prologue: fill stages 0..1 with chunks 0..1 ----
    #pragma unroll
    for (int i = 0; i < NSTAGE - 1; i++) {
        uint32_t sA = sbase + i * STAGE_BYTES;
        uint32_t sB = sA + A_STAGE_BYTES;
        #pragma unroll
        for (int j = 0; j < 8; j++) {
            cp16(sA + d_off[j], a_src[j] + i * BKF);
            cp16(sB + d_off[j], b_src[j] + i * BKF);
        }
        cp_commit();
    }

    // ---- fragment addressing (tile-invariant) ----
    const int asel = lane & 7;
    const int aRowBase = wm + (lane & 7) + ((lane >> 3) & 1) * 8;
    const int aCLane   = (lane >> 4) & 1;
    const int bRowBase = wn + (lane & 7) + ((lane >> 4) & 1) * 8;
    const int bCLane   = (lane >> 3) & 1;

    uint32_t aRowOff[4], bRowOff[4];
    #pragma unroll
    for (int mi = 0; mi < 4; mi++) aRowOff[mi] = (uint32_t)((aRowBase + mi * 16) * 128);
    #pragma unroll
    for (int p = 0; p < 4; p++)    bRowOff[p]  = (uint32_t)((bRowBase + p * 16) * 128);

    uint32_t cA[4], cB[4];
    #pragma unroll
    for (int ks = 0; ks < 4; ks++) {
        cA[ks] = (uint32_t)((((2 * ks + aCLane) ^ asel)) << 4);
        cB[ks] = (uint32_t)((((2 * ks + bCLane) ^ asel)) << 4);
    }

    float acc[4][8][4];
    #pragma unroll
    for (int mi = 0; mi < 4; mi++)
        #pragma unroll
        for (int ni = 0; ni < 8; ni++)
            #pragma unroll
            for (int r = 0; r < 4; r++)
                acc[mi][ni][r] = 0.0f;

    // Double-buffered fragments (ping-pong across ks)
    uint32_t afr[2][4][4], bfr[2][8][2];

    // ---- main loop over 32 K-chunks ----
    for (int i = 0; i < NCHUNK; i++) {
        cp_wait1();
        __syncthreads();

        int nx = i + NSTAGE - 1;
        if (nx < NCHUNK) {
            uint32_t sA = sbase + (nx % NSTAGE) * STAGE_BYTES;
            uint32_t sB = sA + A_STAGE_BYTES;
            #pragma unroll
            for (int j = 0; j < 8; j++) {
                cp16(sA + d_off[j], a_src[j] + nx * BKF);
                cp16(sB + d_off[j], b_src[j] + nx * BKF);
            }
        }
        cp_commit();

        const uint32_t sA = sbase + (i % NSTAGE) * STAGE_BYTES;
        const uint32_t sB = sA + A_STAGE_BYTES;

        // preload ks=0 fragments
        #pragma unroll
        for (int mi = 0; mi < 4; mi++)
            ldsm4(afr[0][mi][0], afr[0][mi][1], afr[0][mi][2], afr[0][mi][3],
                  sA + aRowOff[mi] + cA[0]);
        #pragma unroll
        for (int p = 0; p < 4; p++) {
            uint32_t t0, t1, t2, t3;
            ldsm4(t0, t1, t2, t3, sB + bRowOff[p] + cB[0]);
            bfr[0][2 * p][0] = t0; bfr[0][2 * p][1] = t1;
            bfr[0][2 * p + 1][0] = t2; bfr[0][2 * p + 1][1] = t3;
        }

        #pragma unroll
        for (int ks = 0; ks < 4; ks++) {
            const int cur = ks & 1;
            const int nxt = cur ^ 1;
            if (ks < 3) {   // prefetch ks+1 fragments; latency hidden by MMAs below
                #pragma unroll
                for (int mi = 0; mi < 4; mi++)
                    ldsm4(afr[nxt][mi][0], afr[nxt][mi][1], afr[nxt][mi][2], afr[nxt][mi][3],
                          sA + aRowOff[mi] + cA[ks + 1]);
                #pragma unroll
                for (int p = 0; p < 4; p++) {
                    uint32_t t0, t1, t2, t3;
                    ldsm4(t0, t1, t2, t3, sB + bRowOff[p] + cB[ks + 1]);
                    bfr[nxt][2 * p][0] = t0; bfr[nxt][2 * p][1] = t1;
                    bfr[nxt][2 * p + 1][0] = t2; bfr[nxt][2 * p + 1][1] = t3;
                }
            }
            #pragma unroll
            for (int mi = 0; mi < 4; mi++)
                #pragma unroll
                for (int ni = 0; ni < 8; ni++)
                    mma_tf32(acc[mi][ni][0], acc[mi][ni][1], acc[mi][ni][2], acc[mi][ni][3],
                             afr[cur][mi][0], afr[cur][mi][1], afr[cur][mi][2], afr[cur][mi][3],
                             bfr[cur][ni][0], bfr[cur][ni][1]);
        }
    }

    // ---- epilogue: scatter valid rows back through perm (streaming stores) ----
    const int q  = lane >> 2;
    const int cc = 2 * (lane & 3);
    #pragma unroll
    for (int mi = 0; mi < 4; mi++) {
        #pragma unroll
        for (int half = 0; half < 2; half++) {
            const int r = wm + mi * 16 + q + half * 8;
            const int m = mt * BM + r;
            if (m < cnt) {
                float* orow = out + (size_t)g_perm[off + m] * OUT_FEAT
                                  + nt * BN + wn + cc;
                #pragma unroll
                for (int ni = 0; ni < 8; ni++)
                    stg_cs_v2(orow + ni * 8,
                              acc[mi][ni][half * 2], acc[mi][ni][half * 2 + 1]);
            }
        }
    }
}

extern "C" void kernel_launch(void* const* d_in, const int* in_sizes, int n_in,
                              void* d_out, int out_size) {
    const float* inp    = (const float*)d_in[0];   // [N_TOKENS, IN_FEAT] f32
    const int*   gate   = (const int*)d_in[1];     // [N_TOKENS] i32
    const float* weight = (const float*)d_in[2];   // [NUM_EXPERT, OUT_FEAT, IN_FEAT] f32
    float* out = (float*)d_out;                    // [N_TOKENS, OUT_FEAT] f32

    cudaFuncSetAttribute(moe_gemm_mma_kernel,
                         cudaFuncAttributeMaxDynamicSharedMemorySize, SMEM_TOTAL);

    build_perm_kernel<<<1, 256>>>(gate);
    gather_cvt_kernel<<<N_TOKENS, 256>>>(inp);

    dim3 grid(OUT_FEAT / BN, N_TOKENS / BM, NUM_EXPERT);
    moe_gemm_mma_kernel<<<grid, NTHREADS, SMEM_TOTAL>>>(weight, out);
}